// round 2
// baseline (speedup 1.0000x reference)
#include <cuda_runtime.h>
#include <cuda_bf16.h>

// y = D @ x per row, D = blockdiag(1024 x [4x4]) + diag(rem[3]).
// x: (ROWS, ROW_LEN) fp32 flattened, ROW_LEN = n_blocks*4 + rem = 4099.
// Thread owns one block index b, keeps 16 weights in registers, loops rows.
// Warp covers 32 consecutive b -> fully coalesced 512B x-read / y-write.

#define BS 4

__global__ void __launch_bounds__(256) block_apply_kernel(
    const float* __restrict__ x,
    const float* __restrict__ blocks,
    float* __restrict__ y,
    int n_blocks, int row_len, int rows_per_cta, int total_rows)
{
    const int b = blockIdx.x * blockDim.x + threadIdx.x;
    if (b >= n_blocks) return;

    // Load this thread's 4x4 block into registers (64 KB total, L1-resident).
    float w00, w01, w02, w03, w10, w11, w12, w13,
          w20, w21, w22, w23, w30, w31, w32, w33;
    {
        const float* bp = blocks + b * (BS * BS);
        w00 = __ldg(bp +  0); w01 = __ldg(bp +  1); w02 = __ldg(bp +  2); w03 = __ldg(bp +  3);
        w10 = __ldg(bp +  4); w11 = __ldg(bp +  5); w12 = __ldg(bp +  6); w13 = __ldg(bp +  7);
        w20 = __ldg(bp +  8); w21 = __ldg(bp +  9); w22 = __ldg(bp + 10); w23 = __ldg(bp + 11);
        w30 = __ldg(bp + 12); w31 = __ldg(bp + 13); w32 = __ldg(bp + 14); w33 = __ldg(bp + 15);
    }

    int row0 = blockIdx.y * rows_per_cta;
    int row1 = row0 + rows_per_cta;
    if (row1 > total_rows) row1 = total_rows;

    const int col = b * BS;

    #pragma unroll 2
    for (int row = row0; row < row1; ++row) {
        // max index ~67.2M < 2^31, int is safe
        int base = row * row_len + col;
        float x0 = x[base + 0];
        float x1 = x[base + 1];
        float x2 = x[base + 2];
        float x3 = x[base + 3];
        y[base + 0] = w00 * x0 + w01 * x1 + w02 * x2 + w03 * x3;
        y[base + 1] = w10 * x0 + w11 * x1 + w12 * x2 + w13 * x3;
        y[base + 2] = w20 * x0 + w21 * x1 + w22 * x2 + w23 * x3;
        y[base + 3] = w30 * x0 + w31 * x1 + w32 * x2 + w33 * x3;
    }
}

// Remainder diagonal region + (defensive) zero tail up to row_len.
__global__ void remainder_kernel(
    const float* __restrict__ x,
    const float* __restrict__ dr,
    float* __restrict__ y,
    int block_region, int rem, int row_len, int total_rows)
{
    int tail = row_len - block_region;          // = rem here (no pad), general-safe
    int i = blockIdx.x * blockDim.x + threadIdx.x;
    int total = total_rows * tail;
    if (i >= total) return;
    int row = i / tail;
    int t   = i - row * tail;
    int idx = row * row_len + block_region + t;
    y[idx] = (t < rem) ? x[idx] * __ldg(dr + t) : 0.0f;
}

extern "C" void kernel_launch(void* const* d_in, const int* in_sizes, int n_in,
                              void* d_out, int out_size)
{
    const float* x      = (const float*)d_in[0];
    const float* blocks = (const float*)d_in[1];
    const float* dr     = (const float*)d_in[2];
    float* y = (float*)d_out;

    const int n_blocks     = in_sizes[1] / (BS * BS);   // 1024
    const int rem          = in_sizes[2];               // 3
    const int block_region = n_blocks * BS;             // 4096
    const int row_len      = block_region + rem;        // 4099
    const int total_rows   = out_size / row_len;        // 16384

    // Main block-region kernel: grid.x covers b, grid.y chunks rows.
    const int THREADS = 256;
    const int gx = (n_blocks + THREADS - 1) / THREADS;  // 4
    int rows_per_cta = 16;
    int gy = (total_rows + rows_per_cta - 1) / rows_per_cta;  // 1024 -> 4096 CTAs
    dim3 grid(gx, gy, 1);
    block_apply_kernel<<<grid, THREADS>>>(x, blocks, y, n_blocks, row_len,
                                          rows_per_cta, total_rows);

    // Remainder region (tiny).
    int tail = row_len - block_region;
    if (tail > 0) {
        int total = total_rows * tail;
        int rb = (total + 255) / 256;
        remainder_kernel<<<rb, 256>>>(x, dr, y, block_region, rem, row_len, total_rows);
    }
}

// round 4
// speedup vs baseline: 1.1368x; 1.1368x over previous
#include <cuda_runtime.h>
#include <cuda_bf16.h>

// y = D @ x per row, D = blockdiag(1024 x [4x4]) + diag(rem[3]).
// x: (ROWS, ROW_LEN) fp32, ROW_LEN = n_blocks*4 + rem = 4099.
// Fused single kernel:
//   threads b < n_blocks : own one 4x4 block (weights in regs via 4x LDG.128),
//                          loop rows, coalesced 512B/warp read+write.
//   thread  b == n_blocks: diagonal remainder tail for the same rows.
// Grid: (ceil((n_blocks+1)/256), rows/ROWS_PER_CTA) -> ~10K CTAs for wave balance.

#define BS 4
#define ROWS_PER_CTA 8

__global__ void __launch_bounds__(256) fused_block_apply_kernel(
    const float* __restrict__ x,
    const float* __restrict__ blocks,
    const float* __restrict__ dr,
    float* __restrict__ y,
    int n_blocks, int rem, int row_len, int total_rows)
{
    const int b = blockIdx.x * blockDim.x + threadIdx.x;
    int row0 = blockIdx.y * ROWS_PER_CTA;
    int row1 = row0 + ROWS_PER_CTA;
    if (row1 > total_rows) row1 = total_rows;

    if (b < n_blocks) {
        // 4x4 weight block: 64 bytes, 64B-aligned -> 4x LDG.128 (L1/L2 resident).
        const float4* bp = reinterpret_cast<const float4*>(blocks) + b * BS;
        const float4 w0 = __ldg(bp + 0);
        const float4 w1 = __ldg(bp + 1);
        const float4 w2 = __ldg(bp + 2);
        const float4 w3 = __ldg(bp + 3);

        // max index ~67.2M < 2^31 -> int addressing safe
        int base = row0 * row_len + b * BS;

        #pragma unroll 4
        for (int row = row0; row < row1; ++row, base += row_len) {
            float x0 = __ldcs(x + base + 0);
            float x1 = __ldcs(x + base + 1);
            float x2 = __ldcs(x + base + 2);
            float x3 = __ldcs(x + base + 3);
            y[base + 0] = w0.x * x0 + w0.y * x1 + w0.z * x2 + w0.w * x3;
            y[base + 1] = w1.x * x0 + w1.y * x1 + w1.z * x2 + w1.w * x3;
            y[base + 2] = w2.x * x0 + w2.y * x1 + w2.z * x2 + w2.w * x3;
            y[base + 3] = w3.x * x0 + w3.y * x1 + w3.z * x2 + w3.w * x3;
        }
    } else if (b == n_blocks) {
        // Diagonal remainder + defensive zero-pad of any extra tail.
        const int colbase = n_blocks * BS;
        const int tail = row_len - colbase;   // == rem for this problem
        int base = row0 * row_len + colbase;
        for (int row = row0; row < row1; ++row, base += row_len) {
            #pragma unroll 3
            for (int t = 0; t < tail; ++t) {
                float v = (t < rem) ? __ldcs(x + base + t) * __ldg(dr + t) : 0.0f;
                y[base + t] = v;
            }
        }
    }
}

extern "C" void kernel_launch(void* const* d_in, const int* in_sizes, int n_in,
                              void* d_out, int out_size)
{
    const float* x      = (const float*)d_in[0];
    const float* blocks = (const float*)d_in[1];
    const float* dr     = (const float*)d_in[2];
    float* y = (float*)d_out;

    const int n_blocks     = in_sizes[1] / (BS * BS);   // 1024
    const int rem          = in_sizes[2];               // 3
    const int block_region = n_blocks * BS;             // 4096
    const int row_len      = block_region + rem;        // 4099
    const int total_rows   = out_size / row_len;        // 16384

    const int THREADS = 256;
    const int gx = (n_blocks + 1 + THREADS - 1) / THREADS;          // 5
    const int gy = (total_rows + ROWS_PER_CTA - 1) / ROWS_PER_CTA;  // 2048
    dim3 grid(gx, gy, 1);
    fused_block_apply_kernel<<<grid, THREADS>>>(x, blocks, dr, y,
                                                n_blocks, rem, row_len, total_rows);
}